// round 9
// baseline (speedup 1.0000x reference)
#include <cuda_runtime.h>
#include <cstring>

// out[m,o] = sum_c |x[m,c] - w[c,o]| + b[o]
//          = 2*sum_c max(x[m,c], w[c,o]) - Sx[m] - Sw[o] + b[o]
// R8's low-issue-slot structure (broadcast x LDS, packed add.rn.f32x2) at
// restored concurrency: 784 blocks (BO=64), 8m x 2o thread tile, 256 thr,
// regs capped for 5 blocks/SM -> ~42 warps/SM to cover LDS latency.

constexpr int C    = 64;    // channels (reduction dim)
constexpr int CP   = 32;    // channels per split-K pass
constexpr int OUTC = 128;   // output channels
constexpr int BM   = 64;    // rows per block
constexpr int BO   = 64;    // output cols per block
constexpr int XS   = 68;    // padded stride for transposed x tile

__device__ __forceinline__ void fadd2(unsigned long long& acc, float a, float b) {
    float2 t = make_float2(a, b);
    unsigned long long tv;
    memcpy(&tv, &t, 8);
    asm("add.rn.f32x2 %0, %0, %1;" : "+l"(acc) : "l"(tv));
}

__global__ __launch_bounds__(256, 5)
void lp1_maxtrick_kernel(const float* __restrict__ x,
                         const float* __restrict__ w,
                         const float* __restrict__ b,
                         float* __restrict__ out)
{
    __shared__ float w_s[CP * BO];   // [c][o]  8 KB per pass
    __shared__ float x_s[CP * XS];   // [c][m]  8.7 KB per pass (transposed)
    __shared__ float sx_s[BM];
    __shared__ float beta_s[BO];

    const int tid   = threadIdx.x;
    const int m_blk = blockIdx.x * BM;
    const int o_blk = blockIdx.y * BO;

    const int o0 = (tid & 31) * 2;   // 32 o-groups, 8B lane stride (conflict-free)
    const int m0 = (tid >> 5) * 8;   // warp-uniform -> broadcast x loads

    unsigned long long acc[8];       // packed (o0, o0+1) sums per m-row
    #pragma unroll
    for (int i = 0; i < 8; ++i) acc[i] = 0ull;

    float beta_acc = (tid < BO) ? b[o_blk + tid] : 0.f;  // -> b[o] - Sw[o]
    float sx_acc   = 0.f;                                // -> Sx[m]

    #pragma unroll
    for (int pass = 0; pass < 2; ++pass) {
        const int cbase = pass * CP;

        // ---- stage w half [CP][BO]: 512 float4 (coalesced) ----
        #pragma unroll
        for (int i = 0; i < 2; ++i) {
            int idx = tid + 256 * i;            // 0..511
            int c   = idx >> 4;                 // 16 float4 per c-row
            int o4  = idx & 15;
            *(float4*)(&w_s[c * BO + o4 * 4]) =
                *(const float4*)(w + (cbase + c) * OUTC + o_blk + o4 * 4);
        }

        // ---- stage x half transposed: 512 float4 ----
        #pragma unroll
        for (int i = 0; i < 2; ++i) {
            int idx = tid + 256 * i;            // 0..511
            int m   = idx >> 3;                 // 8 float4 per row (CP=32)
            int c   = (idx & 7) << 2;
            float4 v = *(const float4*)(x + (size_t)(m_blk + m) * C + cbase + c);
            x_s[(c + 0) * XS + m] = v.x;
            x_s[(c + 1) * XS + m] = v.y;
            x_s[(c + 2) * XS + m] = v.z;
            x_s[(c + 3) * XS + m] = v.w;
        }
        __syncthreads();

        // ---- prologue partials ----
        if (tid < BO) {
            #pragma unroll
            for (int c = 0; c < CP; ++c) beta_acc -= w_s[c * BO + tid];
        } else if (tid < BO + BM) {
            int m = tid - BO;
            #pragma unroll
            for (int c = 0; c < CP; ++c) sx_acc += x_s[c * XS + m];
        }

        // ---- main loop: 8(m) x 2(o), broadcast x + LDS.64 w ----
        #pragma unroll 16
        for (int c = 0; c < CP; ++c) {
            float4 xv0 = *(const float4*)(&x_s[c * XS + m0]);      // broadcast
            float4 xv1 = *(const float4*)(&x_s[c * XS + m0 + 4]);  // broadcast
            float2 wv  = *(const float2*)(&w_s[c * BO + o0]);      // 8B stride
            float xa[8] = {xv0.x, xv0.y, xv0.z, xv0.w,
                           xv1.x, xv1.y, xv1.z, xv1.w};
            #pragma unroll
            for (int i = 0; i < 8; ++i)
                fadd2(acc[i], fmaxf(xa[i], wv.x), fmaxf(xa[i], wv.y));
        }
        __syncthreads();   // protect restage of next pass
    }

    // ---- publish corrections ----
    if (tid < BO)            beta_s[tid]       = beta_acc;
    else if (tid < BO + BM)  sx_s[tid - BO]    = sx_acc;
    __syncthreads();

    // ---- epilogue: out = 2*acc - sx + beta ----
    const float bet0 = beta_s[o0];
    const float bet1 = beta_s[o0 + 1];

    #pragma unroll
    for (int i = 0; i < 8; ++i) {
        float base = -sx_s[m0 + i];
        float2 p;
        memcpy(&p, &acc[i], 8);
        float2 r;
        r.x = fmaf(2.f, p.x, base + bet0);
        r.y = fmaf(2.f, p.y, base + bet1);
        *(float2*)(out + (size_t)(m_blk + m0 + i) * OUTC + o_blk + o0) = r;
    }
}

extern "C" void kernel_launch(void* const* d_in, const int* in_sizes, int n_in,
                              void* d_out, int out_size)
{
    const float* x = (const float*)d_in[0];   // [M, 64]
    const float* w = (const float*)d_in[1];   // [64, 128]
    const float* b = (const float*)d_in[2];   // [128]
    float* out = (float*)d_out;               // [M, 128]

    int M = in_sizes[0] / C;                  // 25088
    dim3 grid(M / BM, OUTC / BO);             // (392, 2) = 784 blocks
    lp1_maxtrick_kernel<<<grid, 256>>>(x, w, b, out);
}